// round 4
// baseline (speedup 1.0000x reference)
#include <cuda_runtime.h>
#include <math.h>

// ===== Problem constants (fixed shapes) =====
#define NB    4
#define LSEQ  8192
#define MTOT  (NB*LSEQ)   // 32768 rows
#define CDIM  256
#define HDIM  512
#define NHEAD 8
#define DHEAD 32

// ===== Scratch (no cudaMalloc allowed; __device__ globals) =====
__device__ float g_qfeat[(size_t)MTOT*CDIM];
__device__ float g_kfeat[(size_t)MTOT*CDIM];
__device__ float g_vproj[(size_t)MTOT*CDIM];
__device__ float g_msg  [(size_t)MTOT*CDIM];
__device__ float g_msgm [(size_t)MTOT*CDIM];
__device__ float g_msgln[(size_t)MTOT*CDIM];
__device__ float g_h1   [(size_t)MTOT*HDIM];
__device__ float g_h2   [(size_t)MTOT*CDIM];
__device__ float g_KV  [NB*NHEAD*DHEAD*DHEAD]; // includes 1/S
__device__ float g_Ksum[NB*NHEAD*DHEAD];

// ===== Activations =====
#define ACT_NONE 0
#define ACT_ELU1 1
#define ACT_RELU 2

template<int ACT>
__device__ __forceinline__ float act_fn(float v) {
    if (ACT == ACT_ELU1) return v > 0.f ? v + 1.f : expf(v); // elu(v)+1
    if (ACT == ACT_RELU) return v > 0.f ? v : 0.f;
    return v;
}

// ===== Tiled fp32 GEMM:  Y[M,NN] = act( X[M,KK] @ W[NN,KK]^T )
// X can be split along K: k<K1 from X1 (row stride K1), k>=K1 from X2 (row stride KK-K1).
// BM=BN=128, BK=16, 256 threads, 8x8 per thread, double-buffered smem.
static const int BM = 128, BN = 128, BK = 16;

template<int ACT, int NN, int KK, int K1>
__device__ __forceinline__ void gemm_body(const float* __restrict__ X1,
                                          const float* __restrict__ X2,
                                          const float* __restrict__ W,
                                          float* __restrict__ Y) {
    __shared__ __align__(16) float As[2][BK][BM];
    __shared__ __align__(16) float Bs[2][BK][BN];

    const int tid = threadIdx.x;         // 0..255
    const int bm  = blockIdx.y * BM;
    const int bn  = blockIdx.x * BN;
    const int lr  = tid >> 2;            // 0..63  (load row)
    const int lc  = (tid & 3) * 4;       // 0,4,8,12 (k offset)
    const int tx  = tid & 15;
    const int ty  = tid >> 4;
    constexpr int K2 = KK - K1;

    float4 xr0, xr1, wr0, wr1;

    auto load_regs = [&](int kt) {
        const int kb = kt * BK;
        if (K1 == KK || kb < K1) {
            const float* xp = X1 + (size_t)(bm + lr) * K1 + kb + lc;
            xr0 = *(const float4*)xp;
            xr1 = *(const float4*)(xp + (size_t)64 * K1);
        } else {
            const float* xp = X2 + (size_t)(bm + lr) * (K2 ? K2 : 1) + (kb - K1) + lc;
            xr0 = *(const float4*)xp;
            xr1 = *(const float4*)(xp + (size_t)64 * K2);
        }
        const float* wp = W + (size_t)(bn + lr) * KK + kb + lc;
        wr0 = *(const float4*)wp;
        wr1 = *(const float4*)(wp + (size_t)64 * KK);
    };

    auto store_smem = [&](int b) {
        As[b][lc+0][lr]    = xr0.x; As[b][lc+1][lr]    = xr0.y;
        As[b][lc+2][lr]    = xr0.z; As[b][lc+3][lr]    = xr0.w;
        As[b][lc+0][lr+64] = xr1.x; As[b][lc+1][lr+64] = xr1.y;
        As[b][lc+2][lr+64] = xr1.z; As[b][lc+3][lr+64] = xr1.w;
        Bs[b][lc+0][lr]    = wr0.x; Bs[b][lc+1][lr]    = wr0.y;
        Bs[b][lc+2][lr]    = wr0.z; Bs[b][lc+3][lr]    = wr0.w;
        Bs[b][lc+0][lr+64] = wr1.x; Bs[b][lc+1][lr+64] = wr1.y;
        Bs[b][lc+2][lr+64] = wr1.z; Bs[b][lc+3][lr+64] = wr1.w;
    };

    float acc[8][8];
    #pragma unroll
    for (int i = 0; i < 8; ++i)
        #pragma unroll
        for (int j = 0; j < 8; ++j) acc[i][j] = 0.f;

    constexpr int NKT = KK / BK;
    load_regs(0);
    store_smem(0);
    __syncthreads();
    int buf = 0;

    for (int kt = 0; kt < NKT; ++kt) {
        if (kt + 1 < NKT) load_regs(kt + 1);
        #pragma unroll
        for (int kk = 0; kk < BK; ++kk) {
            float a[8], b[8];
            *(float4*)&a[0] = *(float4*)&As[buf][kk][ty*4];
            *(float4*)&a[4] = *(float4*)&As[buf][kk][64 + ty*4];
            *(float4*)&b[0] = *(float4*)&Bs[buf][kk][tx*4];
            *(float4*)&b[4] = *(float4*)&Bs[buf][kk][64 + tx*4];
            #pragma unroll
            for (int i = 0; i < 8; ++i)
                #pragma unroll
                for (int j = 0; j < 8; ++j)
                    acc[i][j] += a[i] * b[j];
        }
        if (kt + 1 < NKT) {
            store_smem(buf ^ 1);
            __syncthreads();
            buf ^= 1;
        }
    }

    #pragma unroll
    for (int i = 0; i < 8; ++i) {
        const int mrow = bm + ((i < 4) ? (ty*4 + i) : (64 + ty*4 + (i - 4)));
        float4 o0, o1;
        o0.x = act_fn<ACT>(acc[i][0]); o0.y = act_fn<ACT>(acc[i][1]);
        o0.z = act_fn<ACT>(acc[i][2]); o0.w = act_fn<ACT>(acc[i][3]);
        o1.x = act_fn<ACT>(acc[i][4]); o1.y = act_fn<ACT>(acc[i][5]);
        o1.z = act_fn<ACT>(acc[i][6]); o1.w = act_fn<ACT>(acc[i][7]);
        *(float4*)&Y[(size_t)mrow * NN + bn + tx*4]      = o0;
        *(float4*)&Y[(size_t)mrow * NN + bn + 64 + tx*4] = o1;
    }
}

// GEMM wrappers (scratch buffers referenced from device code — no symbol lookups needed)
__global__ void __launch_bounds__(256, 2) k_gemm_q(const float* X, const float* W) {
    gemm_body<ACT_ELU1, 256, 256, 256>(X, nullptr, W, g_qfeat);
}
__global__ void __launch_bounds__(256, 2) k_gemm_k(const float* X, const float* W) {
    gemm_body<ACT_ELU1, 256, 256, 256>(X, nullptr, W, g_kfeat);
}
__global__ void __launch_bounds__(256, 2) k_gemm_v(const float* X, const float* W) {
    gemm_body<ACT_NONE, 256, 256, 256>(X, nullptr, W, g_vproj);
}
__global__ void __launch_bounds__(256, 2) k_gemm_m(const float* W) {
    gemm_body<ACT_NONE, 256, 256, 256>(g_msg, nullptr, W, g_msgm);
}
__global__ void __launch_bounds__(256, 2) k_gemm_1(const float* X, const float* W) {
    // h1 = relu([x | msg_ln] @ W1^T), K split at 256 (concat never materialized)
    gemm_body<ACT_RELU, 512, 512, 256>(X, g_msgln, W, g_h1);
}
__global__ void __launch_bounds__(256, 2) k_gemm_2(const float* W) {
    gemm_body<ACT_NONE, 256, 512, 512>(g_h1, nullptr, W, g_h2);
}

// ===== zero KV/Ksum accumulators =====
__global__ void zero_kv_kernel() {
    const int i = blockIdx.x * 256 + threadIdx.x;
    if (i < NB*NHEAD*DHEAD*DHEAD) g_KV[i] = 0.f;
    if (i < NB*NHEAD*DHEAD)       g_Ksum[i] = 0.f;
}

// ===== KV = sum_s K[s,h,d] * v[s,h,v] / S ;  Ksum = sum_s K =====
// grid (16 splits, 8 heads, 4 batch), 256 threads. thread = (d0=tid>>5, v=tid&31),
// owns d in {d0, d0+8, d0+16, d0+24}. atomicAdd partials.
__global__ void __launch_bounds__(256) kv_reduce_kernel() {
    const int split = blockIdx.x, h = blockIdx.y, n = blockIdx.z;
    __shared__ __align__(16) float sk[64][32];
    __shared__ __align__(16) float sv[64][32];
    const int tid = threadIdx.x;
    const int v  = tid & 31;
    const int d0 = tid >> 5;

    float kv[4] = {0.f, 0.f, 0.f, 0.f};
    float ks[4] = {0.f, 0.f, 0.f, 0.f};

    const int ROWS = LSEQ / 16; // 512 per block
    const int srow0 = n * LSEQ + split * ROWS;

    for (int s0 = 0; s0 < ROWS; s0 += 64) {
        __syncthreads();
        #pragma unroll
        for (int t = 0; t < 2; ++t) {
            const int i = tid + t * 256;        // float4 index 0..511
            const int r = i >> 3, c = (i & 7) * 4;
            const size_t gidx = (size_t)(srow0 + s0 + r) * CDIM + h * DHEAD + c;
            *(float4*)&sk[r][c] = *(const float4*)&g_kfeat[gidx];
            *(float4*)&sv[r][c] = *(const float4*)&g_vproj[gidx];
        }
        __syncthreads();
        for (int r = 0; r < 64; ++r) {
            const float vv = sv[r][v];
            #pragma unroll
            for (int q = 0; q < 4; ++q) {
                const float kd = sk[r][d0 + 8*q];   // warp-broadcast
                kv[q] += kd * vv;
                ks[q] += kd;
            }
        }
    }
    #pragma unroll
    for (int q = 0; q < 4; ++q) {
        const int d = d0 + 8*q;
        atomicAdd(&g_KV[(((size_t)n*NHEAD + h)*DHEAD + d)*DHEAD + v],
                  kv[q] * (1.0f / (float)LSEQ));
        if (v == 0)
            atomicAdd(&g_Ksum[((size_t)n*NHEAD + h)*DHEAD + d], ks[q]);
    }
}

// ===== msg[l, h*32+v] = (Q_h . KV_h[:,v]) * S / (Q_h . Ksum_h + 1e-6) =====
__global__ void __launch_bounds__(256) attn_kernel() {
    const int n = blockIdx.y;
    __shared__ __align__(16) float sKV[NHEAD*DHEAD*DHEAD]; // 8192 floats = 32KB
    __shared__ float sKs[NHEAD*DHEAD];                     // 256 floats
    const int tid = threadIdx.x;

    for (int i = tid; i < NHEAD*DHEAD*DHEAD/4; i += 256)
        *(float4*)&sKV[i*4] = *(const float4*)&g_KV[(size_t)n*NHEAD*DHEAD*DHEAD + i*4];
    sKs[tid] = g_Ksum[n*NHEAD*DHEAD + tid];
    __syncthreads();

    const size_t row = (size_t)n * LSEQ + (size_t)blockIdx.x * 256 + tid;
    const float* qrow = g_qfeat + row * CDIM;
    float*       mrow = g_msg   + row * CDIM;

    for (int h = 0; h < NHEAD; ++h) {
        float Q[DHEAD];
        #pragma unroll
        for (int i = 0; i < 8; ++i)
            *(float4*)&Q[i*4] = *(const float4*)&qrow[h*DHEAD + i*4];

        float zden = 1e-6f;
        #pragma unroll
        for (int d = 0; d < DHEAD; ++d) zden += Q[d] * sKs[h*DHEAD + d];
        const float z = (float)LSEQ / zden;

        #pragma unroll
        for (int v4 = 0; v4 < 8; ++v4) {
            float ax = 0.f, ay = 0.f, az = 0.f, aw = 0.f;
            #pragma unroll
            for (int d = 0; d < DHEAD; ++d) {
                const float4 kv = *(const float4*)&sKV[(h*DHEAD + d)*DHEAD + v4*4];
                const float qd = Q[d];
                ax += qd * kv.x; ay += qd * kv.y; az += qd * kv.z; aw += qd * kv.w;
            }
            float4 o; o.x = ax*z; o.y = ay*z; o.z = az*z; o.w = aw*z;
            *(float4*)&mrow[h*DHEAD + v4*4] = o;
        }
    }
}

// ===== LayerNorm over last dim (256), warp-per-row; optional residual add =====
template<bool ADDX>
__device__ __forceinline__ void ln_body(const float* __restrict__ in,
                                        const float* __restrict__ gamma,
                                        const float* __restrict__ beta,
                                        const float* __restrict__ xres,
                                        float* __restrict__ out) {
    const int w = threadIdx.x >> 5, lane = threadIdx.x & 31;
    const size_t row = (size_t)blockIdx.x * 8 + w;
    const float* p = in + row * CDIM;

    const float4 v0 = *(const float4*)&p[lane*4];
    const float4 v1 = *(const float4*)&p[128 + lane*4];

    float s  = v0.x + v0.y + v0.z + v0.w + v1.x + v1.y + v1.z + v1.w;
    float s2 = v0.x*v0.x + v0.y*v0.y + v0.z*v0.z + v0.w*v0.w
             + v1.x*v1.x + v1.y*v1.y + v1.z*v1.z + v1.w*v1.w;
    #pragma unroll
    for (int o = 16; o; o >>= 1) {
        s  += __shfl_xor_sync(0xFFFFFFFFu, s,  o);
        s2 += __shfl_xor_sync(0xFFFFFFFFu, s2, o);
    }
    const float mu  = s * (1.f / 256.f);
    const float var = s2 * (1.f / 256.f) - mu * mu;
    const float rs  = rsqrtf(var + 1e-5f);

    const float4 gm0 = *(const float4*)&gamma[lane*4];
    const float4 gm1 = *(const float4*)&gamma[128 + lane*4];
    const float4 bt0 = *(const float4*)&beta[lane*4];
    const float4 bt1 = *(const float4*)&beta[128 + lane*4];

    float4 o0, o1;
    o0.x = (v0.x - mu)*rs*gm0.x + bt0.x;  o0.y = (v0.y - mu)*rs*gm0.y + bt0.y;
    o0.z = (v0.z - mu)*rs*gm0.z + bt0.z;  o0.w = (v0.w - mu)*rs*gm0.w + bt0.w;
    o1.x = (v1.x - mu)*rs*gm1.x + bt1.x;  o1.y = (v1.y - mu)*rs*gm1.y + bt1.y;
    o1.z = (v1.z - mu)*rs*gm1.z + bt1.z;  o1.w = (v1.w - mu)*rs*gm1.w + bt1.w;

    if (ADDX) {
        const float4 x0 = *(const float4*)&xres[row*CDIM + lane*4];
        const float4 x1 = *(const float4*)&xres[row*CDIM + 128 + lane*4];
        o0.x += x0.x; o0.y += x0.y; o0.z += x0.z; o0.w += x0.w;
        o1.x += x1.x; o1.y += x1.y; o1.z += x1.z; o1.w += x1.w;
    }
    *(float4*)&out[row*CDIM + lane*4]       = o0;
    *(float4*)&out[row*CDIM + 128 + lane*4] = o1;
}

__global__ void __launch_bounds__(256) k_ln1(const float* g, const float* b) {
    ln_body<false>(g_msgm, g, b, nullptr, g_msgln);
}
__global__ void __launch_bounds__(256) k_ln2(const float* g, const float* b,
                                             const float* x, float* out) {
    ln_body<true>(g_h2, g, b, x, out);
}

// ===== Launch =====
extern "C" void kernel_launch(void* const* d_in, const int* in_sizes, int n_in,
                              void* d_out, int out_size) {
    const float* x    = (const float*)d_in[0];
    const float* src  = (const float*)d_in[1];
    const float* Wq   = (const float*)d_in[2];
    const float* Wk   = (const float*)d_in[3];
    const float* Wv   = (const float*)d_in[4];
    const float* Wm   = (const float*)d_in[5];
    const float* ln1g = (const float*)d_in[6];
    const float* ln1b = (const float*)d_in[7];
    const float* W1   = (const float*)d_in[8];
    const float* W2   = (const float*)d_in[9];
    const float* ln2g = (const float*)d_in[10];
    const float* ln2b = (const float*)d_in[11];
    float* out = (float*)d_out;

    const dim3 blk(256);
    const dim3 gq(CDIM / BN, MTOT / BM);   // (2, 256)
    const dim3 g1(HDIM / BN, MTOT / BM);   // (4, 256)

    zero_kv_kernel<<<128, 256>>>();
    k_gemm_q<<<gq, blk>>>(x, Wq);          // qfeat = elu(x Wq^T)+1
    k_gemm_k<<<gq, blk>>>(src, Wk);        // kfeat = elu(src Wk^T)+1
    k_gemm_v<<<gq, blk>>>(src, Wv);        // vproj = src Wv^T
    kv_reduce_kernel<<<dim3(16, NHEAD, NB), 256>>>();
    attn_kernel<<<dim3(LSEQ / 256, NB), 256>>>();
    k_gemm_m<<<gq, blk>>>(Wm);             // msgm = msg Wm^T
    k_ln1<<<MTOT / 8, 256>>>(ln1g, ln1b);  // msg_ln = LN1(msgm)
    k_gemm_1<<<g1, blk>>>(x, W1);          // h1 = relu([x|msg_ln] W1^T)
    k_gemm_2<<<gq, blk>>>(W2);             // h2 = h1 W2^T
    k_ln2<<<MTOT / 8, 256>>>(ln2g, ln2b, x, out); // out = x + LN2(h2)
}

// round 6
// speedup vs baseline: 1.0505x; 1.0505x over previous
#include <cuda_runtime.h>
#include <math.h>

// ===== Problem constants (fixed shapes) =====
#define NB    4
#define LSEQ  8192
#define MTOT  (NB*LSEQ)   // 32768 rows
#define CDIM  256
#define HDIM  512
#define NHEAD 8
#define DHEAD 32

// ===== Scratch (no cudaMalloc allowed; __device__ globals) =====
__device__ float g_qfeat[(size_t)MTOT*CDIM];
__device__ float g_kfeat[(size_t)MTOT*CDIM];
__device__ float g_vproj[(size_t)MTOT*CDIM];
__device__ float g_msg  [(size_t)MTOT*CDIM];
__device__ float g_msgm [(size_t)MTOT*CDIM];
__device__ float g_msgln[(size_t)MTOT*CDIM];
__device__ float g_h1   [(size_t)MTOT*HDIM];
__device__ float g_h2   [(size_t)MTOT*CDIM];
__device__ float g_KV  [NB*NHEAD*DHEAD*DHEAD]; // includes 1/S
__device__ float g_Ksum[NB*NHEAD*DHEAD];

// ===== Activations =====
#define ACT_NONE 0
#define ACT_ELU1 1
#define ACT_RELU 2

template<int ACT>
__device__ __forceinline__ float act_fn(float v) {
    if (ACT == ACT_ELU1) return v > 0.f ? v + 1.f : expf(v); // elu(v)+1
    if (ACT == ACT_RELU) return v > 0.f ? v : 0.f;
    return v;
}

// ===== packed f32x2 helpers (sm_100+: fma.rn.f32x2 = SASS FFMA2) =====
__device__ __forceinline__ unsigned long long dup_f2(float v) {
    unsigned long long r;
    asm("mov.b64 %0, {%1, %1};" : "=l"(r) : "f"(v));
    return r;
}
__device__ __forceinline__ void fma_f32x2(unsigned long long &d,
                                          unsigned long long a,
                                          unsigned long long b) {
    asm("fma.rn.f32x2 %0, %1, %2, %0;" : "+l"(d) : "l"(a), "l"(b));
}
__device__ __forceinline__ float2 unpk_f2(unsigned long long v) {
    float2 r;
    asm("mov.b64 {%0, %1}, %2;" : "=f"(r.x), "=f"(r.y) : "l"(v));
    return r;
}

// ===== Tiled fp32 GEMM:  Y[M,NN] = act( X[M,KK] @ W[NN,KK]^T )
// X can be split along K: k<K1 from X1 (row stride K1), k>=K1 from X2 (row stride KK-K1).
// BM=BN=128, BK=16, 256 threads, 8x8 per thread, double-buffered smem.
// Inner product uses FFMA2: accumulators packed as row-pairs (M direction),
// A-pairs fall out of the 128-bit smem loads for free, B scalars duplicated
// via mov.b64 (ALU pipe, dual-issues against FMA pipe).
static const int BM = 128, BN = 128, BK = 16;

template<int ACT, int NN, int KK, int K1>
__device__ __forceinline__ void gemm_body(const float* __restrict__ X1,
                                          const float* __restrict__ X2,
                                          const float* __restrict__ W,
                                          float* __restrict__ Y) {
    __shared__ __align__(16) float As[2][BK][BM];
    __shared__ __align__(16) float Bs[2][BK][BN];

    const int tid = threadIdx.x;         // 0..255
    const int bm  = blockIdx.y * BM;
    const int bn  = blockIdx.x * BN;
    const int lr  = tid >> 2;            // 0..63  (load row)
    const int lc  = (tid & 3) * 4;       // 0,4,8,12 (k offset)
    const int tx  = tid & 15;
    const int ty  = tid >> 4;
    constexpr int K2 = KK - K1;

    float4 xr0, xr1, wr0, wr1;

    auto load_regs = [&](int kt) {
        const int kb = kt * BK;
        if (K1 == KK || kb < K1) {
            const float* xp = X1 + (size_t)(bm + lr) * K1 + kb + lc;
            xr0 = *(const float4*)xp;
            xr1 = *(const float4*)(xp + (size_t)64 * K1);
        } else {
            const float* xp = X2 + (size_t)(bm + lr) * (K2 ? K2 : 1) + (kb - K1) + lc;
            xr0 = *(const float4*)xp;
            xr1 = *(const float4*)(xp + (size_t)64 * K2);
        }
        const float* wp = W + (size_t)(bn + lr) * KK + kb + lc;
        wr0 = *(const float4*)wp;
        wr1 = *(const float4*)(wp + (size_t)64 * KK);
    };

    auto store_smem = [&](int b) {
        As[b][lc+0][lr]    = xr0.x; As[b][lc+1][lr]    = xr0.y;
        As[b][lc+2][lr]    = xr0.z; As[b][lc+3][lr]    = xr0.w;
        As[b][lc+0][lr+64] = xr1.x; As[b][lc+1][lr+64] = xr1.y;
        As[b][lc+2][lr+64] = xr1.z; As[b][lc+3][lr+64] = xr1.w;
        Bs[b][lc+0][lr]    = wr0.x; Bs[b][lc+1][lr]    = wr0.y;
        Bs[b][lc+2][lr]    = wr0.z; Bs[b][lc+3][lr]    = wr0.w;
        Bs[b][lc+0][lr+64] = wr1.x; Bs[b][lc+1][lr+64] = wr1.y;
        Bs[b][lc+2][lr+64] = wr1.z; Bs[b][lc+3][lr+64] = wr1.w;
    };

    // Packed accumulators: accp[i2][j] = (acc[2*i2][j], acc[2*i2+1][j])
    // i2 = 0,1 -> rows ty*4 + {0,1},{2,3};  i2 = 2,3 -> rows 64+ty*4 + {0,1},{2,3}
    unsigned long long accp[4][8];
    #pragma unroll
    for (int i2 = 0; i2 < 4; ++i2)
        #pragma unroll
        for (int j = 0; j < 8; ++j) accp[i2][j] = 0ull;

    constexpr int NKT = KK / BK;
    load_regs(0);
    store_smem(0);
    __syncthreads();
    int buf = 0;

    for (int kt = 0; kt < NKT; ++kt) {
        if (kt + 1 < NKT) load_regs(kt + 1);
        #pragma unroll
        for (int kk = 0; kk < BK; ++kk) {
            // A row-pairs: 128-bit loads give two 64-bit packed pairs each
            const ulonglong2 a0 = *(const ulonglong2*)&As[buf][kk][ty*4];
            const ulonglong2 a1 = *(const ulonglong2*)&As[buf][kk][64 + ty*4];
            const unsigned long long ap[4] = {a0.x, a0.y, a1.x, a1.y};
            // B scalars, duplicated into both f32x2 lanes
            const float4 b0 = *(const float4*)&Bs[buf][kk][tx*4];
            const float4 b1 = *(const float4*)&Bs[buf][kk][64 + tx*4];
            unsigned long long bd[8];
            bd[0] = dup_f2(b0.x); bd[1] = dup_f2(b0.y);
            bd[2] = dup_f2(b0.z); bd[3] = dup_f2(b0.w);
            bd[4] = dup_f2(b1.x); bd[5] = dup_f2(b1.y);
            bd[6] = dup_f2(b1.z); bd[7] = dup_f2(b1.w);
            #pragma unroll
            for (int i2 = 0; i2 < 4; ++i2)
                #pragma unroll
                for (int j = 0; j < 8; ++j)
                    fma_f32x2(accp[i2][j], ap[i2], bd[j]);
        }
        if (kt + 1 < NKT) {
            store_smem(buf ^ 1);
            __syncthreads();
            buf ^= 1;
        }
    }

    // Unpack to scalar accumulator grid (i index matches previous layout)
    float acc[8][8];
    #pragma unroll
    for (int i2 = 0; i2 < 4; ++i2)
        #pragma unroll
        for (int j = 0; j < 8; ++j) {
            const float2 p = unpk_f2(accp[i2][j]);
            acc[2*i2 + 0][j] = p.x;
            acc[2*i2 + 1][j] = p.y;
        }

    #pragma unroll
    for (int i = 0; i < 8; ++i) {
        const int mrow = bm + ((i < 4) ? (ty*4 + i) : (64 + ty*4 + (i - 4)));
        float4 o0, o1;
        o0.x = act_fn<ACT>(acc[i][0]); o0.y = act_fn<ACT>(acc[i][1]);
        o0.z = act_fn<ACT>(acc[i][2]); o0.w = act_fn<ACT>(acc[i][3]);
        o1.x = act_fn<ACT>(acc[i][4]); o1.y = act_fn<ACT>(acc[i][5]);
        o1.z = act_fn<ACT>(acc[i][6]); o1.w = act_fn<ACT>(acc[i][7]);
        *(float4*)&Y[(size_t)mrow * NN + bn + tx*4]      = o0;
        *(float4*)&Y[(size_t)mrow * NN + bn + 64 + tx*4] = o1;
    }
}

// GEMM wrappers
__global__ void __launch_bounds__(256, 2) k_gemm_q(const float* X, const float* W) {
    gemm_body<ACT_ELU1, 256, 256, 256>(X, nullptr, W, g_qfeat);
}
__global__ void __launch_bounds__(256, 2) k_gemm_k(const float* X, const float* W) {
    gemm_body<ACT_ELU1, 256, 256, 256>(X, nullptr, W, g_kfeat);
}
__global__ void __launch_bounds__(256, 2) k_gemm_v(const float* X, const float* W) {
    gemm_body<ACT_NONE, 256, 256, 256>(X, nullptr, W, g_vproj);
}
__global__ void __launch_bounds__(256, 2) k_gemm_m(const float* W) {
    gemm_body<ACT_NONE, 256, 256, 256>(g_msg, nullptr, W, g_msgm);
}
__global__ void __launch_bounds__(256, 2) k_gemm_1(const float* X, const float* W) {
    // h1 = relu([x | msg_ln] @ W1^T), K split at 256 (concat never materialized)
    gemm_body<ACT_RELU, 512, 512, 256>(X, g_msgln, W, g_h1);
}
__global__ void __launch_bounds__(256, 2) k_gemm_2(const float* W) {
    gemm_body<ACT_NONE, 256, 512, 512>(g_h1, nullptr, W, g_h2);
}

// ===== zero KV/Ksum accumulators =====
__global__ void zero_kv_kernel() {
    const int i = blockIdx.x * 256 + threadIdx.x;
    if (i < NB*NHEAD*DHEAD*DHEAD) g_KV[i] = 0.f;
    if (i < NB*NHEAD*DHEAD)       g_Ksum[i] = 0.f;
}

// ===== KV = sum_s K[s,h,d] * v[s,h,v] / S ;  Ksum = sum_s K =====
__global__ void __launch_bounds__(256) kv_reduce_kernel() {
    const int split = blockIdx.x, h = blockIdx.y, n = blockIdx.z;
    __shared__ __align__(16) float sk[64][32];
    __shared__ __align__(16) float sv[64][32];
    const int tid = threadIdx.x;
    const int v  = tid & 31;
    const int d0 = tid >> 5;

    float kv[4] = {0.f, 0.f, 0.f, 0.f};
    float ks[4] = {0.f, 0.f, 0.f, 0.f};

    const int ROWS = LSEQ / 16; // 512 per block
    const int srow0 = n * LSEQ + split * ROWS;

    for (int s0 = 0; s0 < ROWS; s0 += 64) {
        __syncthreads();
        #pragma unroll
        for (int t = 0; t < 2; ++t) {
            const int i = tid + t * 256;        // float4 index 0..511
            const int r = i >> 3, c = (i & 7) * 4;
            const size_t gidx = (size_t)(srow0 + s0 + r) * CDIM + h * DHEAD + c;
            *(float4*)&sk[r][c] = *(const float4*)&g_kfeat[gidx];
            *(float4*)&sv[r][c] = *(const float4*)&g_vproj[gidx];
        }
        __syncthreads();
        for (int r = 0; r < 64; ++r) {
            const float vv = sv[r][v];
            #pragma unroll
            for (int q = 0; q < 4; ++q) {
                const float kd = sk[r][d0 + 8*q];   // warp-broadcast
                kv[q] += kd * vv;
                ks[q] += kd;
            }
        }
    }
    #pragma unroll
    for (int q = 0; q < 4; ++q) {
        const int d = d0 + 8*q;
        atomicAdd(&g_KV[(((size_t)n*NHEAD + h)*DHEAD + d)*DHEAD + v],
                  kv[q] * (1.0f / (float)LSEQ));
        if (v == 0)
            atomicAdd(&g_Ksum[((size_t)n*NHEAD + h)*DHEAD + d], ks[q]);
    }
}

// ===== msg[l, h*32+v] = (Q_h . KV_h[:,v]) * S / (Q_h . Ksum_h + 1e-6) =====
__global__ void __launch_bounds__(256) attn_kernel() {
    const int n = blockIdx.y;
    __shared__ __align__(16) float sKV[NHEAD*DHEAD*DHEAD]; // 8192 floats = 32KB
    __shared__ float sKs[NHEAD*DHEAD];                     // 256 floats
    const int tid = threadIdx.x;

    for (int i = tid; i < NHEAD*DHEAD*DHEAD/4; i += 256)
        *(float4*)&sKV[i*4] = *(const float4*)&g_KV[(size_t)n*NHEAD*DHEAD*DHEAD + i*4];
    sKs[tid] = g_Ksum[n*NHEAD*DHEAD + tid];
    __syncthreads();

    const size_t row = (size_t)n * LSEQ + (size_t)blockIdx.x * 256 + tid;
    const float* qrow = g_qfeat + row * CDIM;
    float*       mrow = g_msg   + row * CDIM;

    for (int h = 0; h < NHEAD; ++h) {
        float Q[DHEAD];
        #pragma unroll
        for (int i = 0; i < 8; ++i)
            *(float4*)&Q[i*4] = *(const float4*)&qrow[h*DHEAD + i*4];

        float zden = 1e-6f;
        #pragma unroll
        for (int d = 0; d < DHEAD; ++d) zden += Q[d] * sKs[h*DHEAD + d];
        const float z = (float)LSEQ / zden;

        #pragma unroll
        for (int v4 = 0; v4 < 8; ++v4) {
            float ax = 0.f, ay = 0.f, az = 0.f, aw = 0.f;
            #pragma unroll
            for (int d = 0; d < DHEAD; ++d) {
                const float4 kv = *(const float4*)&sKV[(h*DHEAD + d)*DHEAD + v4*4];
                const float qd = Q[d];
                ax += qd * kv.x; ay += qd * kv.y; az += qd * kv.z; aw += qd * kv.w;
            }
            float4 o; o.x = ax*z; o.y = ay*z; o.z = az*z; o.w = aw*z;
            *(float4*)&mrow[h*DHEAD + v4*4] = o;
        }
    }
}

// ===== LayerNorm over last dim (256), warp-per-row; optional residual add =====
template<bool ADDX>
__device__ __forceinline__ void ln_body(const float* __restrict__ in,
                                        const float* __restrict__ gamma,
                                        const float* __restrict__ beta,
                                        const float* __restrict__ xres,
                                        float* __restrict__ out) {
    const int w = threadIdx.x >> 5, lane = threadIdx.x & 31;
    const size_t row = (size_t)blockIdx.x * 8 + w;
    const float* p = in + row * CDIM;

    const float4 v0 = *(const float4*)&p[lane*4];
    const float4 v1 = *(const float4*)&p[128 + lane*4];

    float s  = v0.x + v0.y + v0.z + v0.w + v1.x + v1.y + v1.z + v1.w;
    float s2 = v0.x*v0.x + v0.y*v0.y + v0.z*v0.z + v0.w*v0.w
             + v1.x*v1.x + v1.y*v1.y + v1.z*v1.z + v1.w*v1.w;
    #pragma unroll
    for (int o = 16; o; o >>= 1) {
        s  += __shfl_xor_sync(0xFFFFFFFFu, s,  o);
        s2 += __shfl_xor_sync(0xFFFFFFFFu, s2, o);
    }
    const float mu  = s * (1.f / 256.f);
    const float var = s2 * (1.f / 256.f) - mu * mu;
    const float rs  = rsqrtf(var + 1e-5f);

    const float4 gm0 = *(const float4*)&gamma[lane*4];
    const float4 gm1 = *(const float4*)&gamma[128 + lane*4];
    const float4 bt0 = *(const float4*)&beta[lane*4];
    const float4 bt1 = *(const float4*)&beta[128 + lane*4];

    float4 o0, o1;
    o0.x = (v0.x - mu)*rs*gm0.x + bt0.x;  o0.y = (v0.y - mu)*rs*gm0.y + bt0.y;
    o0.z = (v0.z - mu)*rs*gm0.z + bt0.z;  o0.w = (v0.w - mu)*rs*gm0.w + bt0.w;
    o1.x = (v1.x - mu)*rs*gm1.x + bt1.x;  o1.y = (v1.y - mu)*rs*gm1.y + bt1.y;
    o1.z = (v1.z - mu)*rs*gm1.z + bt1.z;  o1.w = (v1.w - mu)*rs*gm1.w + bt1.w;

    if (ADDX) {
        const float4 x0 = *(const float4*)&xres[row*CDIM + lane*4];
        const float4 x1 = *(const float4*)&xres[row*CDIM + 128 + lane*4];
        o0.x += x0.x; o0.y += x0.y; o0.z += x0.z; o0.w += x0.w;
        o1.x += x1.x; o1.y += x1.y; o1.z += x1.z; o1.w += x1.w;
    }
    *(float4*)&out[row*CDIM + lane*4]       = o0;
    *(float4*)&out[row*CDIM + 128 + lane*4] = o1;
}

__global__ void __launch_bounds__(256) k_ln1(const float* g, const float* b) {
    ln_body<false>(g_msgm, g, b, nullptr, g_msgln);
}
__global__ void __launch_bounds__(256) k_ln2(const float* g, const float* b,
                                             const float* x, float* out) {
    ln_body<true>(g_h2, g, b, x, out);
}

// ===== Launch =====
extern "C" void kernel_launch(void* const* d_in, const int* in_sizes, int n_in,
                              void* d_out, int out_size) {
    const float* x    = (const float*)d_in[0];
    const float* src  = (const float*)d_in[1];
    const float* Wq   = (const float*)d_in[2];
    const float* Wk   = (const float*)d_in[3];
    const float* Wv   = (const float*)d_in[4];
    const float* Wm   = (const float*)d_in[5];
    const float* ln1g = (const float*)d_in[6];
    const float* ln1b = (const float*)d_in[7];
    const float* W1   = (const float*)d_in[8];
    const float* W2   = (const float*)d_in[9];
    const float* ln2g = (const float*)d_in[10];
    const float* ln2b = (const float*)d_in[11];
    float* out = (float*)d_out;

    const dim3 blk(256);
    const dim3 gq(CDIM / BN, MTOT / BM);   // (2, 256)
    const dim3 g1(HDIM / BN, MTOT / BM);   // (4, 256)

    zero_kv_kernel<<<128, 256>>>();
    k_gemm_q<<<gq, blk>>>(x, Wq);          // qfeat = elu(x Wq^T)+1
    k_gemm_k<<<gq, blk>>>(src, Wk);        // kfeat = elu(src Wk^T)+1
    k_gemm_v<<<gq, blk>>>(src, Wv);        // vproj = src Wv^T
    kv_reduce_kernel<<<dim3(16, NHEAD, NB), 256>>>();
    attn_kernel<<<dim3(LSEQ / 256, NB), 256>>>();
    k_gemm_m<<<gq, blk>>>(Wm);             // msgm = msg Wm^T
    k_ln1<<<MTOT / 8, 256>>>(ln1g, ln1b);  // msg_ln = LN1(msgm)
    k_gemm_1<<<g1, blk>>>(x, W1);          // h1 = relu([x|msg_ln] W1^T)
    k_gemm_2<<<gq, blk>>>(W2);             // h2 = h1 W2^T
    k_ln2<<<MTOT / 8, 256>>>(ln2g, ln2b, x, out); // out = x + LN2(h2)
}

// round 11
// speedup vs baseline: 1.5130x; 1.4402x over previous
#include <cuda_runtime.h>
#include <cuda_bf16.h>
#include <mma.h>
#include <math.h>
#include <stdint.h>

using namespace nvcuda;

// ===== Problem constants (fixed shapes) =====
#define NB    4
#define LSEQ  8192
#define MTOT  (NB*LSEQ)   // 32768 rows
#define CDIM  256
#define HDIM  512
#define NHEAD 8
#define DHEAD 32

// ===== Scratch (no cudaMalloc; __device__ globals) =====
__device__ __align__(128) float g_qraw [(size_t)MTOT*CDIM]; // x@Wq^T (pre-ELU)
__device__ __align__(128) float g_kraw [(size_t)MTOT*CDIM]; // src@Wk^T (pre-ELU)
__device__ __align__(128) float g_vproj[(size_t)MTOT*CDIM];
__device__ __align__(128) float g_msgm [(size_t)MTOT*CDIM];
__device__ __align__(128) float g_h1f  [(size_t)MTOT*HDIM]; // pre-ReLU h1
__device__ __align__(128) float g_h2   [(size_t)MTOT*CDIM];
__device__ float g_KV  [NB*NHEAD*DHEAD*DHEAD]; // includes 1/S
__device__ float g_Ksum[NB*NHEAD*DHEAD];
// bf16 split-2 "cat3" operands: X-side = [hi | lo | hi], W-side = [hi | hi | lo]
// single GEMM over 3K computes hi*hi + lo*hi + hi*lo  (only lo*lo ~2^-16 dropped)
__device__ __align__(128) __nv_bfloat16 g_xcat [(size_t)MTOT*3*CDIM]; // x        [M,768]
__device__ __align__(128) __nv_bfloat16 g_scat [(size_t)MTOT*3*CDIM]; // source   [M,768]
__device__ __align__(128) __nv_bfloat16 g_mcat [(size_t)MTOT*3*CDIM]; // message  [M,768]
__device__ __align__(128) __nv_bfloat16 g_g1in [(size_t)MTOT*3*HDIM]; // [x|msgln][M,1536]
__device__ __align__(128) __nv_bfloat16 g_h1cat[(size_t)MTOT*3*HDIM]; // relu h1  [M,1536]
__device__ __align__(128) __nv_bfloat16 g_wqcat[(size_t)CDIM*3*CDIM];
__device__ __align__(128) __nv_bfloat16 g_wkcat[(size_t)CDIM*3*CDIM];
__device__ __align__(128) __nv_bfloat16 g_wvcat[(size_t)CDIM*3*CDIM];
__device__ __align__(128) __nv_bfloat16 g_wmcat[(size_t)CDIM*3*CDIM];
__device__ __align__(128) __nv_bfloat16 g_w1cat[(size_t)HDIM*3*HDIM];
__device__ __align__(128) __nv_bfloat16 g_w2cat[(size_t)CDIM*3*HDIM];

__device__ __forceinline__ float elu1(float v) {
    return v > 0.f ? v + 1.f : expf(v); // elu(v)+1
}

// ===== helpers =====
__device__ __forceinline__ uint32_t smem_u32(const void* p) {
    uint32_t a;
    asm("{ .reg .u64 t; cvta.to.shared.u64 t, %1; cvt.u32.u64 %0, t; }" : "=r"(a) : "l"(p));
    return a;
}
__device__ __forceinline__ void cpasync16(uint32_t s, const void* g) {
    asm volatile("cp.async.cg.shared.global [%0], [%1], 16;" :: "r"(s), "l"(g) : "memory");
}
// bf16 hi/lo split
__device__ __forceinline__ void split_bf16(float v, __nv_bfloat16& h, __nv_bfloat16& l) {
    h = __float2bfloat16(v);
    l = __float2bfloat16(v - __bfloat162float(h));
}

// ===== WMMA GEMM:  Y[M,NN] = Xcat[M,K3] @ Wcat[NN,K3]^T  (raw fp32 out) =====
// CTA 128x128, 128 threads (4 warps, 2x2), warp tile 64x64 (16 acc frags).
// BK=32, padded smem rows (ld=40 bf16 = 80B -> conflict-free ldmatrix),
// simple 2-stage cp.async double buffer. All fragment layouts via wmma API.
#define BKW 32
#define LDP 40   // BKW + 8 pad; 80B rows, multiple of 16B

template<int NN, int K3>
__device__ __forceinline__ void wmma_body(const __nv_bfloat16* __restrict__ X,
                                          const __nv_bfloat16* __restrict__ Wc,
                                          float* __restrict__ Y) {
    __shared__ __align__(128) __nv_bfloat16 As[2][128][LDP]; // 2*10240B
    __shared__ __align__(128) __nv_bfloat16 Bs[2][128][LDP];

    const int tid = threadIdx.x;     // 0..127
    const int wid = tid >> 5;        // 0..3
    const int bm  = blockIdx.y * 128;
    const int bn  = blockIdx.x * 128;
    const int wm  = (wid & 1) * 64;
    const int wn  = (wid >> 1) * 64;
    constexpr int NC = K3 / BKW;

    auto load_stage = [&](int c, int st) {
        #pragma unroll
        for (int i = tid; i < 512; i += 128) {   // 128 rows x 4 chunks of 16B
            const int r  = i >> 2;
            const int ch = i & 3;
            cpasync16(smem_u32(&As[st][r][ch * 8]),
                      X  + (size_t)(bm + r) * K3 + c * BKW + ch * 8);
            cpasync16(smem_u32(&Bs[st][r][ch * 8]),
                      Wc + (size_t)(bn + r) * K3 + c * BKW + ch * 8);
        }
        asm volatile("cp.async.commit_group;" ::: "memory");
    };

    wmma::fragment<wmma::accumulator, 16, 16, 16, float> acc[4][4];
    #pragma unroll
    for (int i = 0; i < 4; ++i)
        #pragma unroll
        for (int j = 0; j < 4; ++j) wmma::fill_fragment(acc[i][j], 0.0f);

    load_stage(0, 0);

    for (int c = 0; c < NC; ++c) {
        asm volatile("cp.async.wait_group 0;" ::: "memory");
        __syncthreads();                  // stage c&1 ready + visible to all warps
        if (c + 1 < NC) load_stage(c + 1, (c + 1) & 1);  // prefetch overlaps compute
        const int st = c & 1;

        #pragma unroll
        for (int kk = 0; kk < BKW / 16; ++kk) {
            wmma::fragment<wmma::matrix_a, 16, 16, 16, __nv_bfloat16, wmma::row_major> af[4];
            wmma::fragment<wmma::matrix_b, 16, 16, 16, __nv_bfloat16, wmma::col_major> bf[4];
            #pragma unroll
            for (int i = 0; i < 4; ++i)
                wmma::load_matrix_sync(af[i], &As[st][wm + i * 16][kk * 16], LDP);
            #pragma unroll
            for (int j = 0; j < 4; ++j)
                wmma::load_matrix_sync(bf[j], &Bs[st][wn + j * 16][kk * 16], LDP);
            #pragma unroll
            for (int i = 0; i < 4; ++i)
                #pragma unroll
                for (int j = 0; j < 4; ++j)
                    wmma::mma_sync(acc[i][j], af[i], bf[j], acc[i][j]);
        }
    }

    #pragma unroll
    for (int i = 0; i < 4; ++i)
        #pragma unroll
        for (int j = 0; j < 4; ++j)
            wmma::store_matrix_sync(
                &Y[(size_t)(bm + wm + i * 16) * NN + bn + wn + j * 16],
                acc[i][j], NN, wmma::mem_row_major);
}

__global__ void __launch_bounds__(128) k_wq() {
    wmma_body<256, 768>(g_xcat, g_wqcat, g_qraw);
}
__global__ void __launch_bounds__(128) k_wk() {
    wmma_body<256, 768>(g_scat, g_wkcat, g_kraw);
}
__global__ void __launch_bounds__(128) k_wv() {
    wmma_body<256, 768>(g_scat, g_wvcat, g_vproj);
}
__global__ void __launch_bounds__(128) k_wm() {
    wmma_body<256, 768>(g_mcat, g_wmcat, g_msgm);
}
__global__ void __launch_bounds__(128) k_w1() {
    wmma_body<512, 1536>(g_g1in, g_w1cat, g_h1f);
}
__global__ void __launch_bounds__(128) k_w2() {
    wmma_body<256, 1536>(g_h1cat, g_w2cat, g_h2);
}

// ===== Conversion kernels (fp32 -> bf16 split cat3) =====
// Weights: Wcat[n, 3K] = [hi | hi | lo].
// CRITICAL: the output device-global is bound INSIDE device code (wrapper
// kernels below). Passing a __device__ global as a host-side kernel argument
// resolves to the host shadow symbol; on GB300 (ATS) the writes silently land
// in host memory and the device copy stays zero — that was the R9/R10 bug.
__device__ __forceinline__ void conv_w_body(const float* __restrict__ W,
                                            __nv_bfloat16* __restrict__ out, int K) {
    const size_t i = (size_t)blockIdx.x * 256 + threadIdx.x; // over N*K/2
    const int kh = K >> 1;
    const size_t row = i / kh;
    const int p = (int)(i % kh) * 2;
    const float2 w = *(const float2*)&W[row * K + p];
    __nv_bfloat16 h0, h1, l0, l1;
    split_bf16(w.x, h0, l0); split_bf16(w.y, h1, l1);
    __nv_bfloat162 hh, ll; hh.x = h0; hh.y = h1; ll.x = l0; ll.y = l1;
    __nv_bfloat16* o = out + row * (size_t)(3 * K);
    *(__nv_bfloat162*)&o[p]         = hh;
    *(__nv_bfloat162*)&o[K + p]     = hh;
    *(__nv_bfloat162*)&o[2 * K + p] = ll;
}
__global__ void k_conv_wq(const float* W) { conv_w_body(W, g_wqcat, CDIM); }
__global__ void k_conv_wk(const float* W) { conv_w_body(W, g_wkcat, CDIM); }
__global__ void k_conv_wv(const float* W) { conv_w_body(W, g_wvcat, CDIM); }
__global__ void k_conv_wm(const float* W) { conv_w_body(W, g_wmcat, CDIM); }
__global__ void k_conv_w1(const float* W) { conv_w_body(W, g_w1cat, HDIM); }
__global__ void k_conv_w2(const float* W) { conv_w_body(W, g_w2cat, HDIM); }

// x: xcat[m,768] = [hi|lo|hi] AND the x-slots of g1in[m,1536]
__global__ void k_conv_x(const float* __restrict__ X) {
    const size_t i = (size_t)blockIdx.x * 256 + threadIdx.x; // over MTOT*128
    const size_t m = i >> 7;
    const int p = (int)(i & 127) * 2;
    const float2 xv = *(const float2*)&X[m * CDIM + p];
    __nv_bfloat16 h0, h1, l0, l1;
    split_bf16(xv.x, h0, l0); split_bf16(xv.y, h1, l1);
    __nv_bfloat162 hh, ll; hh.x = h0; hh.y = h1; ll.x = l0; ll.y = l1;
    __nv_bfloat16* xc = g_xcat + m * 768;
    *(__nv_bfloat162*)&xc[p]       = hh;
    *(__nv_bfloat162*)&xc[256 + p] = ll;
    *(__nv_bfloat162*)&xc[512 + p] = hh;
    __nv_bfloat16* g1 = g_g1in + m * 1536;
    *(__nv_bfloat162*)&g1[p]        = hh;
    *(__nv_bfloat162*)&g1[512 + p]  = ll;
    *(__nv_bfloat162*)&g1[1024 + p] = hh;
}
// source: scat[m,768] = [hi|lo|hi]
__global__ void k_conv_s(const float* __restrict__ S) {
    const size_t i = (size_t)blockIdx.x * 256 + threadIdx.x;
    const size_t m = i >> 7;
    const int p = (int)(i & 127) * 2;
    const float2 sv = *(const float2*)&S[m * CDIM + p];
    __nv_bfloat16 h0, h1, l0, l1;
    split_bf16(sv.x, h0, l0); split_bf16(sv.y, h1, l1);
    __nv_bfloat162 hh, ll; hh.x = h0; hh.y = h1; ll.x = l0; ll.y = l1;
    __nv_bfloat16* sc = g_scat + m * 768;
    *(__nv_bfloat162*)&sc[p]       = hh;
    *(__nv_bfloat162*)&sc[256 + p] = ll;
    *(__nv_bfloat162*)&sc[512 + p] = hh;
}
// h1: relu(g_h1f) -> h1cat [hi|lo|hi]
__global__ void k_conv_h1() {
    const size_t i = (size_t)blockIdx.x * 256 + threadIdx.x; // over MTOT*256
    const size_t m = i >> 8;
    const int p = (int)(i & 255) * 2;
    float2 v = *(const float2*)&g_h1f[m * HDIM + p];
    v.x = v.x > 0.f ? v.x : 0.f;
    v.y = v.y > 0.f ? v.y : 0.f;
    __nv_bfloat16 h0, h1, l0, l1;
    split_bf16(v.x, h0, l0); split_bf16(v.y, h1, l1);
    __nv_bfloat162 hh, ll; hh.x = h0; hh.y = h1; ll.x = l0; ll.y = l1;
    __nv_bfloat16* o = g_h1cat + m * 1536;
    *(__nv_bfloat162*)&o[p]          = hh;
    *(__nv_bfloat162*)&o[512 + p]    = ll;
    *(__nv_bfloat162*)&o[1024 + p]   = hh;
}

// ===== zero KV/Ksum accumulators =====
__global__ void zero_kv_kernel() {
    const int i = blockIdx.x * 256 + threadIdx.x;
    if (i < NB*NHEAD*DHEAD*DHEAD) g_KV[i] = 0.f;
    if (i < NB*NHEAD*DHEAD)       g_Ksum[i] = 0.f;
}

// ===== KV = sum_s elu1(K)[s,h,d] * v[s,h,v] / S ;  Ksum = sum_s elu1(K) =====
__global__ void __launch_bounds__(256) kv_reduce_kernel() {
    const int split = blockIdx.x, h = blockIdx.y, n = blockIdx.z;
    __shared__ __align__(16) float sk[64][32];
    __shared__ __align__(16) float sv[64][32];
    const int tid = threadIdx.x;
    const int v  = tid & 31;
    const int d0 = tid >> 5;

    float kv[4] = {0.f, 0.f, 0.f, 0.f};
    float ks[4] = {0.f, 0.f, 0.f, 0.f};

    const int ROWS = LSEQ / 16;
    const int srow0 = n * LSEQ + split * ROWS;

    for (int s0 = 0; s0 < ROWS; s0 += 64) {
        __syncthreads();
        #pragma unroll
        for (int t = 0; t < 2; ++t) {
            const int i = tid + t * 256;
            const int r = i >> 3, c = (i & 7) * 4;
            const size_t gidx = (size_t)(srow0 + s0 + r) * CDIM + h * DHEAD + c;
            float4 kf = *(const float4*)&g_kraw[gidx];
            kf.x = elu1(kf.x); kf.y = elu1(kf.y);
            kf.z = elu1(kf.z); kf.w = elu1(kf.w);
            *(float4*)&sk[r][c] = kf;
            *(float4*)&sv[r][c] = *(const float4*)&g_vproj[gidx];
        }
        __syncthreads();
        for (int r = 0; r < 64; ++r) {
            const float vv = sv[r][v];
            #pragma unroll
            for (int q = 0; q < 4; ++q) {
                const float kd = sk[r][d0 + 8*q];
                kv[q] += kd * vv;
                ks[q] += kd;
            }
        }
    }
    #pragma unroll
    for (int q = 0; q < 4; ++q) {
        const int d = d0 + 8*q;
        atomicAdd(&g_KV[(((size_t)n*NHEAD + h)*DHEAD + d)*DHEAD + v],
                  kv[q] * (1.0f / (float)LSEQ));
        if (v == 0)
            atomicAdd(&g_Ksum[((size_t)n*NHEAD + h)*DHEAD + d], ks[q]);
    }
}

// ===== attention: Q=elu1(qraw); msg -> cat3 bf16 directly =====
__global__ void __launch_bounds__(256) attn_kernel() {
    const int n = blockIdx.y;
    __shared__ __align__(16) float sKV[NHEAD*DHEAD*DHEAD];
    __shared__ float sKs[NHEAD*DHEAD];
    const int tid = threadIdx.x;

    for (int i = tid; i < NHEAD*DHEAD*DHEAD/4; i += 256)
        *(float4*)&sKV[i*4] = *(const float4*)&g_KV[(size_t)n*NHEAD*DHEAD*DHEAD + i*4];
    sKs[tid] = g_Ksum[n*NHEAD*DHEAD + tid];
    __syncthreads();

    const size_t row = (size_t)n * LSEQ + (size_t)blockIdx.x * 256 + tid;
    const float* qrow = g_qraw + row * CDIM;
    __nv_bfloat16* mr = g_mcat + row * 768;

    for (int h = 0; h < NHEAD; ++h) {
        float Q[DHEAD];
        #pragma unroll
        for (int i = 0; i < 8; ++i)
            *(float4*)&Q[i*4] = *(const float4*)&qrow[h*DHEAD + i*4];
        #pragma unroll
        for (int d = 0; d < DHEAD; ++d) Q[d] = elu1(Q[d]);

        float zden = 1e-6f;
        #pragma unroll
        for (int d = 0; d < DHEAD; ++d) zden += Q[d] * sKs[h*DHEAD + d];
        const float z = (float)LSEQ / zden;

        #pragma unroll
        for (int v4 = 0; v4 < 8; ++v4) {
            float ax = 0.f, ay = 0.f, az = 0.f, aw = 0.f;
            #pragma unroll
            for (int d = 0; d < DHEAD; ++d) {
                const float4 kv = *(const float4*)&sKV[(h*DHEAD + d)*DHEAD + v4*4];
                const float qd = Q[d];
                ax += qd * kv.x; ay += qd * kv.y; az += qd * kv.z; aw += qd * kv.w;
            }
            const float o0 = ax*z, o1 = ay*z, o2 = az*z, o3 = aw*z;
            __nv_bfloat16 h0,h1,h2,h3,l0,l1,l2,l3;
            split_bf16(o0,h0,l0); split_bf16(o1,h1,l1);
            split_bf16(o2,h2,l2); split_bf16(o3,h3,l3);
            __nv_bfloat162 ha,hb,la,lb;
            ha.x=h0; ha.y=h1; hb.x=h2; hb.y=h3;
            la.x=l0; la.y=l1; lb.x=l2; lb.y=l3;
            const int col = h*DHEAD + v4*4;
            *(__nv_bfloat162*)&mr[col]           = ha;
            *(__nv_bfloat162*)&mr[col + 2]       = hb;
            *(__nv_bfloat162*)&mr[256 + col]     = la;
            *(__nv_bfloat162*)&mr[256 + col + 2] = lb;
            *(__nv_bfloat162*)&mr[512 + col]     = ha;
            *(__nv_bfloat162*)&mr[512 + col + 2] = hb;
        }
    }
}

// ===== LN1: LayerNorm(g_msgm) -> msg slots of g1in (cat3 bf16) =====
__global__ void __launch_bounds__(256) k_ln1(const float* __restrict__ gamma,
                                             const float* __restrict__ beta) {
    const int w = threadIdx.x >> 5, lane = threadIdx.x & 31;
    const size_t row = (size_t)blockIdx.x * 8 + w;
    const float* p = g_msgm + row * CDIM;

    const float4 v0 = *(const float4*)&p[lane*4];
    const float4 v1 = *(const float4*)&p[128 + lane*4];

    float s  = v0.x + v0.y + v0.z + v0.w + v1.x + v1.y + v1.z + v1.w;
    float s2 = v0.x*v0.x + v0.y*v0.y + v0.z*v0.z + v0.w*v0.w
             + v1.x*v1.x + v1.y*v1.y + v1.z*v1.z + v1.w*v1.w;
    #pragma unroll
    for (int o = 16; o; o >>= 1) {
        s  += __shfl_xor_sync(0xFFFFFFFFu, s,  o);
        s2 += __shfl_xor_sync(0xFFFFFFFFu, s2, o);
    }
    const float mu  = s * (1.f / 256.f);
    const float var = s2 * (1.f / 256.f) - mu * mu;
    const float rs  = rsqrtf(var + 1e-5f);

    __nv_bfloat16* g1 = g_g1in + row * 1536;
    #pragma unroll
    for (int half = 0; half < 2; ++half) {
        const float4 v = half ? v1 : v0;
        const int k = half * 128 + lane * 4;
        const float4 gm = *(const float4*)&gamma[k];
        const float4 bt = *(const float4*)&beta[k];
        const float o0 = (v.x - mu)*rs*gm.x + bt.x;
        const float o1 = (v.y - mu)*rs*gm.y + bt.y;
        const float o2 = (v.z - mu)*rs*gm.z + bt.z;
        const float o3 = (v.w - mu)*rs*gm.w + bt.w;
        __nv_bfloat16 h0,h1,h2,h3,l0,l1,l2,l3;
        split_bf16(o0,h0,l0); split_bf16(o1,h1,l1);
        split_bf16(o2,h2,l2); split_bf16(o3,h3,l3);
        __nv_bfloat162 ha,hb,la,lb;
        ha.x=h0; ha.y=h1; hb.x=h2; hb.y=h3;
        la.x=l0; la.y=l1; lb.x=l2; lb.y=l3;
        // msg occupies cols [256,512) of each 512-wide segment
        *(__nv_bfloat162*)&g1[256 + k]        = ha;
        *(__nv_bfloat162*)&g1[256 + k + 2]    = hb;
        *(__nv_bfloat162*)&g1[768 + k]        = la;
        *(__nv_bfloat162*)&g1[768 + k + 2]    = lb;
        *(__nv_bfloat162*)&g1[1280 + k]       = ha;
        *(__nv_bfloat162*)&g1[1280 + k + 2]   = hb;
    }
}

// ===== LN2 + residual: out = x + LN(g_h2) =====
__global__ void __launch_bounds__(256) k_ln2(const float* __restrict__ gamma,
                                             const float* __restrict__ beta,
                                             const float* __restrict__ xres,
                                             float* __restrict__ out) {
    const int w = threadIdx.x >> 5, lane = threadIdx.x & 31;
    const size_t row = (size_t)blockIdx.x * 8 + w;
    const float* p = g_h2 + row * CDIM;

    const float4 v0 = *(const float4*)&p[lane*4];
    const float4 v1 = *(const float4*)&p[128 + lane*4];

    float s  = v0.x + v0.y + v0.z + v0.w + v1.x + v1.y + v1.z + v1.w;
    float s2 = v0.x*v0.x + v0.y*v0.y + v0.z*v0.z + v0.w*v0.w
             + v1.x*v1.x + v1.y*v1.y + v1.z*v1.z + v1.w*v1.w;
    #pragma unroll
    for (int o = 16; o; o >>= 1) {
        s  += __shfl_xor_sync(0xFFFFFFFFu, s,  o);
        s2 += __shfl_xor_sync(0xFFFFFFFFu, s2, o);
    }
    const float mu  = s * (1.f / 256.f);
    const float var = s2 * (1.f / 256.f) - mu * mu;
    const float rs  = rsqrtf(var + 1e-5f);

    const float4 gm0 = *(const float4*)&gamma[lane*4];
    const float4 gm1 = *(const float4*)&gamma[128 + lane*4];
    const float4 bt0 = *(const float4*)&beta[lane*4];
    const float4 bt1 = *(const float4*)&beta[128 + lane*4];
    const float4 x0  = *(const float4*)&xres[row*CDIM + lane*4];
    const float4 x1  = *(const float4*)&xres[row*CDIM + 128 + lane*4];

    float4 o0, o1;
    o0.x = x0.x + (v0.x - mu)*rs*gm0.x + bt0.x;  o0.y = x0.y + (v0.y - mu)*rs*gm0.y + bt0.y;
    o0.z = x0.z + (v0.z - mu)*rs*gm0.z + bt0.z;  o0.w = x0.w + (v0.w - mu)*rs*gm0.w + bt0.w;
    o1.x = x1.x + (v1.x - mu)*rs*gm1.x + bt1.x;  o1.y = x1.y + (v1.y - mu)*rs*gm1.y + bt1.y;
    o1.z = x1.z + (v1.z - mu)*rs*gm1.z + bt1.z;  o1.w = x1.w + (v1.w - mu)*rs*gm1.w + bt1.w;

    *(float4*)&out[row*CDIM + lane*4]       = o0;
    *(float4*)&out[row*CDIM + 128 + lane*4] = o1;
}

// ===== Launch =====
extern "C" void kernel_launch(void* const* d_in, const int* in_sizes, int n_in,
                              void* d_out, int out_size) {
    const float* x    = (const float*)d_in[0];
    const float* src  = (const float*)d_in[1];
    const float* Wq   = (const float*)d_in[2];
    const float* Wk   = (const float*)d_in[3];
    const float* Wv   = (const float*)d_in[4];
    const float* Wm   = (const float*)d_in[5];
    const float* ln1g = (const float*)d_in[6];
    const float* ln1b = (const float*)d_in[7];
    const float* W1   = (const float*)d_in[8];
    const float* W2   = (const float*)d_in[9];
    const float* ln2g = (const float*)d_in[10];
    const float* ln2b = (const float*)d_in[11];
    float* out = (float*)d_out;

    const dim3 blk(128);
    const dim3 gq(256 / 128, MTOT / 128);   // (2, 256)
    const dim3 g1(512 / 128, MTOT / 128);   // (4, 256)

    // conversions (weights may change per call; always rebuild).
    // Output globals bound in device code — only harness pointers cross host->device.
    k_conv_wq<<<(CDIM*CDIM/2 + 255)/256, 256>>>(Wq);
    k_conv_wk<<<(CDIM*CDIM/2 + 255)/256, 256>>>(Wk);
    k_conv_wv<<<(CDIM*CDIM/2 + 255)/256, 256>>>(Wv);
    k_conv_wm<<<(CDIM*CDIM/2 + 255)/256, 256>>>(Wm);
    k_conv_w1<<<(HDIM*HDIM/2 + 255)/256, 256>>>(W1);
    k_conv_w2<<<(CDIM*HDIM/2 + 255)/256, 256>>>(W2);
    k_conv_x<<<(size_t)MTOT*128/256, 256>>>(x);
    k_conv_s<<<(size_t)MTOT*128/256, 256>>>(src);

    zero_kv_kernel<<<128, 256>>>();
    k_wq<<<gq, blk>>>();                   // qraw = x Wq^T
    k_wk<<<gq, blk>>>();                   // kraw = src Wk^T
    k_wv<<<gq, blk>>>();                   // vproj = src Wv^T
    kv_reduce_kernel<<<dim3(16, NHEAD, NB), 256>>>();   // elu applied on K here
    attn_kernel<<<dim3(LSEQ / 256, NB), 256>>>();       // elu on Q; msg -> g_mcat
    k_wm<<<gq, blk>>>();                   // msgm = msg Wm^T
    k_ln1<<<MTOT / 8, 256>>>(ln1g, ln1b);  // -> g1in msg slots (cat3)
    k_w1<<<g1, blk>>>();                   // h1f = [x|msgln] W1^T (pre-relu)
    k_conv_h1<<<(size_t)MTOT*256/256, 256>>>();         // relu + cat3 -> h1cat
    k_w2<<<gq, blk>>>();                   // h2 = relu(h1) W2^T
    k_ln2<<<MTOT / 8, 256>>>(ln2g, ln2b, x, out);
}